// round 14
// baseline (speedup 1.0000x reference)
#include <cuda_runtime.h>
#include <cuda_fp16.h>
#include <cstdint>

#define B_ 8
#define N_ 2048
#define H_ 256
#define M_TOT (B_ * N_)  // 16384

// ---------------------------------------------------------------------------
// Device scratch (fp16 everywhere)
// ---------------------------------------------------------------------------
__device__ __half g_Gf16[(size_t)B_ * N_ * N_];
__device__ __half g_Xt[(size_t)B_ * H_ * N_];
__device__ __half g_Xt2[(size_t)B_ * H_ * N_];
__device__ __half g_Nf[(size_t)M_TOT * H_];
__device__ __half g_W1[H_ * H_];
__device__ __half g_W2[H_ * H_];
__device__ __half g_Wo[H_ * 2 * H_];
__device__ float  g_dinv[B_ * N_];

// ---------------------------------------------------------------------------
// PTX helpers (sm_80-portable only)
// ---------------------------------------------------------------------------
__device__ __forceinline__ uint32_t s2u(const void* p) {
    uint32_t r;
    asm("{ .reg .u64 t; cvta.to.shared.u64 t, %1; cvt.u32.u64 %0, t; }"
        : "=r"(r) : "l"(p));
    return r;
}
__device__ __forceinline__ void cp16(uint32_t s, const void* g) {
    asm volatile("cp.async.cg.shared.global [%0], [%1], 16;" :: "r"(s), "l"(g) : "memory");
}
#define CP_COMMIT() asm volatile("cp.async.commit_group;" ::: "memory")
#define CP_WAITG2() asm volatile("cp.async.wait_group 2;" ::: "memory")
#define CP_WAITG1() asm volatile("cp.async.wait_group 1;" ::: "memory")
#define CP_WAITG0() asm volatile("cp.async.wait_group 0;" ::: "memory")

__device__ __forceinline__ void ldsm4(uint32_t* r, uint32_t a) {
    asm volatile("ldmatrix.sync.aligned.m8n8.x4.shared.b16 {%0,%1,%2,%3}, [%4];"
                 : "=r"(r[0]), "=r"(r[1]), "=r"(r[2]), "=r"(r[3]) : "r"(a));
}
__device__ __forceinline__ void mma_f16(float* d, const uint32_t* a, const uint32_t* b) {
    asm volatile(
        "mma.sync.aligned.m16n8k16.row.col.f32.f16.f16.f32 "
        "{%0,%1,%2,%3}, {%4,%5,%6,%7}, {%8,%9}, {%0,%1,%2,%3};"
        : "+f"(d[0]), "+f"(d[1]), "+f"(d[2]), "+f"(d[3])
        : "r"(a[0]), "r"(a[1]), "r"(a[2]), "r"(a[3]), "r"(b[0]), "r"(b[1]));
}
__device__ __forceinline__ uint32_t packh2(float a, float b) {
    __half2 t(__float2half_rn(a), __float2half_rn(b));
    return *reinterpret_cast<uint32_t*>(&t);
}

// ---------------------------------------------------------------------------
// graph -> fp16 + fused row-sum -> dinv
// ---------------------------------------------------------------------------
__global__ void graph_conv(const float* __restrict__ graph) {
    int row = blockIdx.x;
    size_t base = (size_t)row * N_;
    float s = 0.f;
#pragma unroll
    for (int it = 0; it < 2; it++) {
        int j = (threadIdx.x + it * 256) * 4;
        float4 v = *(const float4*)(graph + base + j);
        s += v.x + v.y + v.z + v.w;
        *(uint2*)(g_Gf16 + base + j) =
            make_uint2(packh2(v.x, v.y), packh2(v.z, v.w));
    }
#pragma unroll
    for (int o = 16; o; o >>= 1) s += __shfl_down_sync(0xffffffffu, s, o);
    __shared__ float ws[8];
    int lane = threadIdx.x & 31, w = threadIdx.x >> 5;
    if (lane == 0) ws[w] = s;
    __syncthreads();
    if (threadIdx.x == 0) {
        float t = 0.f;
#pragma unroll
        for (int i = 0; i < 8; i++) t += ws[i];
        g_dinv[row] = rsqrtf(t);
    }
}

// ---------------------------------------------------------------------------
// prep_node: one read of node -> Xt (transposed * dinv) AND Nf (row-major)
// ---------------------------------------------------------------------------
__global__ void prep_node(const float* __restrict__ node) {
    __shared__ float t[32][33];
    int b = blockIdx.z, k0 = blockIdx.x * 32, n0 = blockIdx.y * 32;
    const float* S = node + (size_t)b * N_ * H_;
    for (int j = threadIdx.y; j < 32; j += 8) {
        float v = S[(size_t)(k0 + j) * H_ + n0 + threadIdx.x];
        g_Nf[(size_t)(b * N_ + k0 + j) * H_ + n0 + threadIdx.x] = __float2half_rn(v);
        t[j][threadIdx.x] = v * g_dinv[b * N_ + k0 + j];
    }
    __syncthreads();
    for (int j = threadIdx.y; j < 32; j += 8) {
        size_t o = (size_t)(b * H_ + n0 + j) * N_ + k0 + threadIdx.x;
        g_Xt[o] = __float2half_rn(t[threadIdx.x][j]);
    }
}

// ---------------------------------------------------------------------------
// wconv: convert W1, W2, Wout fp32 -> fp16 in one kernel
// ---------------------------------------------------------------------------
__global__ void wconv(const float* __restrict__ W1, const float* __restrict__ W2,
                      const float* __restrict__ Wo) {
    int e = (blockIdx.x * 256 + threadIdx.x) * 4;
    const float* src;
    __half* dst;
    int off;
    if (e < 65536)       { src = W1; dst = g_W1; off = e; }
    else if (e < 131072) { src = W2; dst = g_W2; off = e - 65536; }
    else                 { src = Wo; dst = g_Wo; off = e - 131072; }
    float4 v = *(const float4*)(src + off);
    *(uint2*)(dst + off) = make_uint2(packh2(v.x, v.y), packh2(v.z, v.w));
}

// ===========================================================================
// Tiling: BM=64, BN=256, 256 threads (8 warps: 2m x 4n, warp tile 32x64),
// 2 CTAs per SM. Mainloop BK=32, 4 stages, prefetch distance 3.
// ===========================================================================
#define LDSP 80                             // mainloop rows: 32 fp16 + pad
#define P_A_PART (64 * LDSP)                // 5120
#define P_B_PART (256 * LDSP)               // 20480
#define P_STAGE (P_A_PART + P_B_PART)       // 25600
#define P_NSTAGE 4                          // 102400 pipeline smem
// FC region (reuses pipeline smem):
#define LDSW 144                            // W rows: 64 fp16 + pad
#define CLD 528                             // C/h/Nf rows: 256 fp16 + pad
#define WB0_OFF 33792                       // 64*528
#define WB1_OFF 70656                       // + 256*144
#define SMEM_ALL 107520                     // + 256*144
#define HT_LD 144                           // transposed h rows: 64 tok + pad

// Batched-fragment MMA step (mi=2 x ni=8, acc[2][8][4])
#define MMA_STEP(a_base, a_ld, koff, wb, kb)                                    \
    do {                                                                        \
        uint32_t Af[2][4], Bf[4][4];                                            \
        _Pragma("unroll")                                                       \
        for (int mi = 0; mi < 2; mi++)                                          \
            ldsm4(Af[mi], (a_base) + (warp_m + mi * 16 + a_row) * (a_ld) +      \
                           (koff) + (kb) + a_cb);                               \
        _Pragma("unroll")                                                       \
        for (int g = 0; g < 4; g++)                                             \
            ldsm4(Bf[g], (wb) + (warp_n + g * 16 + b_row) * (LDSW_RT) + (kb) + b_cb); \
        _Pragma("unroll")                                                       \
        for (int g = 0; g < 4; g++)                                             \
            _Pragma("unroll")                                                   \
            for (int mi = 0; mi < 2; mi++) {                                    \
                mma_f16(acc[mi][2 * g],     Af[mi], Bf[g]);                     \
                mma_f16(acc[mi][2 * g + 1], Af[mi], Bf[g] + 2);                 \
            }                                                                   \
    } while (0)

// ===========================================================================
// MODE 0: aggfc1 — C = dinv*(G@Xt^T); h = relu(C@W1^T+b1); Xt2 = h^T*dinv
// MODE 1: aggfc2 — C = dinv*(G@Xt2^T); h = relu(C@W2^T+b2);
//                  out = relu([Nf|h]@Wo^T + bout) (f32)
// ===========================================================================
template <int MODE>
__global__ void __launch_bounds__(256, 2) aggfc(
    const __half* __restrict__ G, const __half* __restrict__ Xin,
    const __half* __restrict__ W, const float* __restrict__ bias,
    const __half* __restrict__ Nf, const __half* __restrict__ Wo,
    const float* __restrict__ bout,
    __half* __restrict__ outh, float* __restrict__ outf)
{
    extern __shared__ char smem[];
    const uint32_t sb = s2u(smem);
    constexpr int NC = N_ / 32;  // 64

    const int tid = threadIdx.x, wid = tid >> 5, lane = tid & 31;
    const int b = blockIdx.z;
    const int m0 = blockIdx.y * 64;
    const int warp_m = (wid & 1) * 32;
    const int warp_n = (wid >> 1) * 64;

    const __half* pA = G + (size_t)b * N_ * N_ + (size_t)m0 * N_;
    const __half* pB = Xin + (size_t)b * H_ * N_;

    float acc[2][8][4];
#pragma unroll
    for (int i = 0; i < 2; i++)
#pragma unroll
        for (int j = 0; j < 8; j++)
#pragma unroll
            for (int q = 0; q < 4; q++) acc[i][j][q] = 0.f;

    // Mainloop stage: A 64 rows x 4 segs + B 256 x 4 = 1280 cp16 (5/thread)
    auto load_stage = [&](int s, int kc) {
        const int k0 = kc * 32;
        const uint32_t base = sb + s * P_STAGE;
#pragma unroll
        for (int it = 0; it < 5; it++) {
            int c = it * 256 + tid;
            if (c < 256) {
                int row = c >> 2, seg = c & 3;
                cp16(base + row * LDSP + seg * 16,
                     pA + (size_t)row * N_ + k0 + seg * 8);
            } else {
                int cb = c - 256;
                int row = cb >> 2, seg = cb & 3;
                cp16(base + P_A_PART + row * LDSP + seg * 16,
                     pB + (size_t)row * N_ + k0 + seg * 8);
            }
        }
    };

    const uint32_t a_row = (uint32_t)(lane & 15);
    const uint32_t a_cb  = (uint32_t)((lane >> 4) * 16);
    const uint32_t b_row = (uint32_t)((lane & 7) + ((lane & 16) ? 8 : 0));
    const uint32_t b_cb  = (uint32_t)((lane & 8) << 1);

    load_stage(0, 0); CP_COMMIT();
    load_stage(1, 1); CP_COMMIT();
    load_stage(2, 2); CP_COMMIT();

    for (int k = 0; k < NC; k++) {
        CP_WAITG2();
        __syncthreads();
        if (k + 3 < NC) load_stage((k + 3) % P_NSTAGE, k + 3);
        CP_COMMIT();

        const uint32_t sA = sb + (k % P_NSTAGE) * P_STAGE;
        const uint32_t sB = sA + P_A_PART;
        {
            const uint32_t LDSW_RT = LDSP;
#pragma unroll
            for (int ks = 0; ks < 2; ks++)
                MMA_STEP(sA, LDSP, 0u, sB, (uint32_t)(ks * 32));
        }
    }

    // ---------------- FC phase: h = relu((dinv.*C) @ W^T + bias) ----------
    __syncthreads();
    CP_WAITG0();

    auto load_w = [&](uint32_t buf, const __half* Wp, int ldw, int kc) {
        const int k0 = kc * 64;
#pragma unroll
        for (int it = 0; it < 8; it++) {
            int c = it * 256 + tid;
            int row = c >> 3, seg = c & 7;
            cp16(buf + row * LDSW + seg * 16,
                 Wp + (size_t)row * ldw + k0 + seg * 8);
        }
    };
    load_w(sb + WB0_OFF, W, H_, 0); CP_COMMIT();
    load_w(sb + WB1_OFF, W, H_, 1); CP_COMMIT();

    const int colb = warp_n + (lane & 3) * 2;
#pragma unroll
    for (int mi = 0; mi < 2; mi++) {
#pragma unroll
        for (int p = 0; p < 2; p++) {
            const int ml = warp_m + mi * 16 + (lane >> 2) + p * 8;
            const float dv = g_dinv[b * N_ + m0 + ml];
#pragma unroll
            for (int ni = 0; ni < 8; ni++) {
                *(uint32_t*)(smem + ml * CLD + (colb + ni * 8) * 2) =
                    packh2(acc[mi][ni][2 * p] * dv, acc[mi][ni][2 * p + 1] * dv);
            }
        }
    }
#pragma unroll
    for (int i = 0; i < 2; i++)
#pragma unroll
        for (int j = 0; j < 8; j++)
#pragma unroll
            for (int q = 0; q < 4; q++) acc[i][j][q] = 0.f;

    CP_WAITG1();
    __syncthreads();

    auto gen_chunk = [&](uint32_t a_base, uint32_t koff, uint32_t wb) {
        const uint32_t LDSW_RT = LDSW;
#pragma unroll
        for (int ks = 0; ks < 4; ks++)
            MMA_STEP(a_base, CLD, koff, wb, (uint32_t)(ks * 32));
    };

    gen_chunk(sb, 0,   sb + WB0_OFF);
    __syncthreads();
    load_w(sb + WB0_OFF, W, H_, 2); CP_COMMIT();
    CP_WAITG1(); __syncthreads();
    gen_chunk(sb, 128, sb + WB1_OFF);
    __syncthreads();
    load_w(sb + WB1_OFF, W, H_, 3); CP_COMMIT();
    CP_WAITG1(); __syncthreads();
    gen_chunk(sb, 256, sb + WB0_OFF);
    CP_WAITG0(); __syncthreads();
    gen_chunk(sb, 384, sb + WB1_OFF);

    if (MODE == 0) {
        // -------- transpose-out: Xt2[b][h][tok] = relu(acc+bias)*dinv -----
        __syncthreads();
#pragma unroll
        for (int mi = 0; mi < 2; mi++) {
#pragma unroll
            for (int p = 0; p < 2; p++) {
                const int ml = warp_m + mi * 16 + (lane >> 2) + p * 8;
                const float dv = g_dinv[b * N_ + m0 + ml];
#pragma unroll
                for (int ni = 0; ni < 8; ni++) {
                    int c = colb + ni * 8;
                    float v0 = fmaxf(acc[mi][ni][2 * p]     + bias[c],     0.f) * dv;
                    float v1 = fmaxf(acc[mi][ni][2 * p + 1] + bias[c + 1], 0.f) * dv;
                    *(__half*)(smem + c * HT_LD + ml * 2)       = __float2half_rn(v0);
                    *(__half*)(smem + (c + 1) * HT_LD + ml * 2) = __float2half_rn(v1);
                }
            }
        }
        __syncthreads();
        // 256 threads: thread t writes h-row t (64 tokens = 128B)
        const char* srow = smem + tid * HT_LD;
        __half* drow = outh + (size_t)(b * H_ + tid) * N_ + m0;
#pragma unroll
        for (int q = 0; q < 8; q++)
            *(uint4*)(drow + q * 8) = *(const uint4*)(srow + q * 16);
    } else {
        // -------- fcout: out = relu([Nf|h] @ Wo^T + bout) ------------------
        __syncthreads();   // all reads of C region done

        // h = relu(acc + bias) -> C region; zero acc
#pragma unroll
        for (int mi = 0; mi < 2; mi++) {
#pragma unroll
            for (int p = 0; p < 2; p++) {
                const int ml = warp_m + mi * 16 + (lane >> 2) + p * 8;
#pragma unroll
                for (int ni = 0; ni < 8; ni++) {
                    int c = colb + ni * 8;
                    *(uint32_t*)(smem + ml * CLD + c * 2) =
                        packh2(fmaxf(acc[mi][ni][2 * p]     + bias[c],     0.f),
                               fmaxf(acc[mi][ni][2 * p + 1] + bias[c + 1], 0.f));
                }
            }
        }
#pragma unroll
        for (int i = 0; i < 2; i++)
#pragma unroll
            for (int j = 0; j < 8; j++)
#pragma unroll
                for (int q = 0; q < 4; q++) acc[i][j][q] = 0.f;

        // Phase A: h-part of concat (Wo k-chunks 4..7)
        load_w(sb + WB0_OFF, Wo, 2 * H_, 4); CP_COMMIT();
        load_w(sb + WB1_OFF, Wo, 2 * H_, 5); CP_COMMIT();
        CP_WAITG1(); __syncthreads();
        gen_chunk(sb, 0,   sb + WB0_OFF);
        __syncthreads();
        load_w(sb + WB0_OFF, Wo, 2 * H_, 6); CP_COMMIT();
        CP_WAITG1(); __syncthreads();
        gen_chunk(sb, 128, sb + WB1_OFF);
        __syncthreads();
        load_w(sb + WB1_OFF, Wo, 2 * H_, 7); CP_COMMIT();
        CP_WAITG1(); __syncthreads();
        gen_chunk(sb, 256, sb + WB0_OFF);
        CP_WAITG0(); __syncthreads();
        gen_chunk(sb, 384, sb + WB1_OFF);

        // Phase B: Nf-part (Wo k-chunks 0..3); Nf tile replaces h in C region
        __syncthreads();   // h fully consumed
        {
            // FIXED: full 256-wide Nf rows — 64 rows x 32 segs = 2048 cp16
#pragma unroll
            for (int it = 0; it < 8; it++) {
                int c = it * 256 + tid;
                int row = c >> 5, seg = c & 31;
                cp16(sb + row * CLD + seg * 16,
                     Nf + (size_t)(b * N_ + m0 + row) * H_ + seg * 8);
            }
        }
        load_w(sb + WB0_OFF, Wo, 2 * H_, 0); CP_COMMIT();   // group: Nf + Wo0
        load_w(sb + WB1_OFF, Wo, 2 * H_, 1); CP_COMMIT();
        CP_WAITG1(); __syncthreads();
        gen_chunk(sb, 0,   sb + WB0_OFF);
        __syncthreads();
        load_w(sb + WB0_OFF, Wo, 2 * H_, 2); CP_COMMIT();
        CP_WAITG1(); __syncthreads();
        gen_chunk(sb, 128, sb + WB1_OFF);
        __syncthreads();
        load_w(sb + WB1_OFF, Wo, 2 * H_, 3); CP_COMMIT();
        CP_WAITG1(); __syncthreads();
        gen_chunk(sb, 256, sb + WB0_OFF);
        CP_WAITG0(); __syncthreads();
        gen_chunk(sb, 384, sb + WB1_OFF);

        // final epilogue: f32 out
#pragma unroll
        for (int mi = 0; mi < 2; mi++) {
#pragma unroll
            for (int p = 0; p < 2; p++) {
                const int ml = warp_m + mi * 16 + (lane >> 2) + p * 8;
                const size_t orow = (size_t)(b * N_ + m0 + ml) * H_;
#pragma unroll
                for (int ni = 0; ni < 8; ni++) {
                    int c = colb + ni * 8;
                    float2 o;
                    o.x = fmaxf(acc[mi][ni][2 * p]     + bout[c],     0.f);
                    o.y = fmaxf(acc[mi][ni][2 * p + 1] + bout[c + 1], 0.f);
                    *(float2*)(outf + orow + c) = o;
                }
            }
        }
    }
}

// ---------------------------------------------------------------------------
// Launch — 5 kernels total
// ---------------------------------------------------------------------------
extern "C" void kernel_launch(void* const* d_in, const int* in_sizes, int n_in,
                              void* d_out, int out_size) {
    const float* node  = (const float*)d_in[0];
    const float* graph = (const float*)d_in[1];
    const float* W1    = (const float*)d_in[2];
    const float* b1    = (const float*)d_in[3];
    const float* W2    = (const float*)d_in[4];
    const float* b2    = (const float*)d_in[5];
    const float* Wout  = (const float*)d_in[6];
    const float* bout  = (const float*)d_in[7];
    float* out = (float*)d_out;

    __half *Gf16, *Xt, *Xt2, *Nf, *W1h, *W2h, *Woh;
    cudaGetSymbolAddress((void**)&Gf16, g_Gf16);
    cudaGetSymbolAddress((void**)&Xt, g_Xt);
    cudaGetSymbolAddress((void**)&Xt2, g_Xt2);
    cudaGetSymbolAddress((void**)&Nf, g_Nf);
    cudaGetSymbolAddress((void**)&W1h, g_W1);
    cudaGetSymbolAddress((void**)&W2h, g_W2);
    cudaGetSymbolAddress((void**)&Woh, g_Wo);

    cudaFuncSetAttribute(aggfc<0>, cudaFuncAttributeMaxDynamicSharedMemorySize, SMEM_ALL);
    cudaFuncSetAttribute(aggfc<1>, cudaFuncAttributeMaxDynamicSharedMemorySize, SMEM_ALL);

    dim3 gAgg(1, N_ / 64, B_);        // 256 CTAs, 2 per SM
    dim3 gXt(64, 8, 8), bXt(32, 8);

    graph_conv<<<B_ * N_, 256>>>(graph);                               // 0
    prep_node<<<gXt, bXt>>>(node);                                     // 1
    wconv<<<256, 256>>>(W1, W2, Wout);                                 // 2
    aggfc<0><<<gAgg, 256, SMEM_ALL>>>(Gf16, Xt, W1h, b1,
                                      nullptr, nullptr, nullptr,
                                      Xt2, nullptr);                   // 3
    aggfc<1><<<gAgg, 256, SMEM_ALL>>>(Gf16, Xt2, W2h, b2,
                                      Nf, Woh, bout,
                                      nullptr, out);                   // 4
}

// round 15
// speedup vs baseline: 1.1402x; 1.1402x over previous
#include <cuda_runtime.h>
#include <cuda_fp16.h>
#include <cstdint>

#define B_ 8
#define N_ 2048
#define H_ 256
#define M_TOT (B_ * N_)  // 16384

// ---------------------------------------------------------------------------
// Device scratch (fp16 everywhere)
// ---------------------------------------------------------------------------
__device__ __half g_Gf16[(size_t)B_ * N_ * N_];
__device__ __half g_Xt[(size_t)B_ * H_ * N_];
__device__ __half g_Xt2[(size_t)B_ * H_ * N_];
__device__ __half g_Nf[(size_t)M_TOT * H_];
__device__ __half g_W1[H_ * H_];
__device__ __half g_W2[H_ * H_];
__device__ __half g_Wo[H_ * 2 * H_];
__device__ float  g_dinv[B_ * N_];

// ---------------------------------------------------------------------------
// PTX helpers (sm_80-portable only)
// ---------------------------------------------------------------------------
__device__ __forceinline__ uint32_t s2u(const void* p) {
    uint32_t r;
    asm("{ .reg .u64 t; cvta.to.shared.u64 t, %1; cvt.u32.u64 %0, t; }"
        : "=r"(r) : "l"(p));
    return r;
}
__device__ __forceinline__ void cp16(uint32_t s, const void* g) {
    asm volatile("cp.async.cg.shared.global [%0], [%1], 16;" :: "r"(s), "l"(g) : "memory");
}
#define CP_COMMIT() asm volatile("cp.async.commit_group;" ::: "memory")
#define CP_WAITG2() asm volatile("cp.async.wait_group 2;" ::: "memory")
#define CP_WAITG1() asm volatile("cp.async.wait_group 1;" ::: "memory")
#define CP_WAITG0() asm volatile("cp.async.wait_group 0;" ::: "memory")

__device__ __forceinline__ void ldsm4(uint32_t* r, uint32_t a) {
    asm volatile("ldmatrix.sync.aligned.m8n8.x4.shared.b16 {%0,%1,%2,%3}, [%4];"
                 : "=r"(r[0]), "=r"(r[1]), "=r"(r[2]), "=r"(r[3]) : "r"(a));
}
__device__ __forceinline__ void mma_f16(float* d, const uint32_t* a, const uint32_t* b) {
    asm volatile(
        "mma.sync.aligned.m16n8k16.row.col.f32.f16.f16.f32 "
        "{%0,%1,%2,%3}, {%4,%5,%6,%7}, {%8,%9}, {%0,%1,%2,%3};"
        : "+f"(d[0]), "+f"(d[1]), "+f"(d[2]), "+f"(d[3])
        : "r"(a[0]), "r"(a[1]), "r"(a[2]), "r"(a[3]), "r"(b[0]), "r"(b[1]));
}
__device__ __forceinline__ uint32_t packh2(float a, float b) {
    __half2 t(__float2half_rn(a), __float2half_rn(b));
    return *reinterpret_cast<uint32_t*>(&t);
}

// ---------------------------------------------------------------------------
// graph -> fp16 + fused row-sum -> dinv
// ---------------------------------------------------------------------------
__global__ void graph_conv(const float* __restrict__ graph) {
    int row = blockIdx.x;
    size_t base = (size_t)row * N_;
    float s = 0.f;
#pragma unroll
    for (int it = 0; it < 2; it++) {
        int j = (threadIdx.x + it * 256) * 4;
        float4 v = *(const float4*)(graph + base + j);
        s += v.x + v.y + v.z + v.w;
        *(uint2*)(g_Gf16 + base + j) =
            make_uint2(packh2(v.x, v.y), packh2(v.z, v.w));
    }
#pragma unroll
    for (int o = 16; o; o >>= 1) s += __shfl_down_sync(0xffffffffu, s, o);
    __shared__ float ws[8];
    int lane = threadIdx.x & 31, w = threadIdx.x >> 5;
    if (lane == 0) ws[w] = s;
    __syncthreads();
    if (threadIdx.x == 0) {
        float t = 0.f;
#pragma unroll
        for (int i = 0; i < 8; i++) t += ws[i];
        g_dinv[row] = rsqrtf(t);
    }
}

// ---------------------------------------------------------------------------
// prep_node: one read of node -> Xt (transposed * dinv) AND Nf (row-major)
// ---------------------------------------------------------------------------
__global__ void prep_node(const float* __restrict__ node) {
    __shared__ float t[32][33];
    int b = blockIdx.z, k0 = blockIdx.x * 32, n0 = blockIdx.y * 32;
    const float* S = node + (size_t)b * N_ * H_;
    for (int j = threadIdx.y; j < 32; j += 8) {
        float v = S[(size_t)(k0 + j) * H_ + n0 + threadIdx.x];
        g_Nf[(size_t)(b * N_ + k0 + j) * H_ + n0 + threadIdx.x] = __float2half_rn(v);
        t[j][threadIdx.x] = v * g_dinv[b * N_ + k0 + j];
    }
    __syncthreads();
    for (int j = threadIdx.y; j < 32; j += 8) {
        size_t o = (size_t)(b * H_ + n0 + j) * N_ + k0 + threadIdx.x;
        g_Xt[o] = __float2half_rn(t[threadIdx.x][j]);
    }
}

// ---------------------------------------------------------------------------
// wconv: convert W1, W2, Wout fp32 -> fp16 in one kernel
// ---------------------------------------------------------------------------
__global__ void wconv(const float* __restrict__ W1, const float* __restrict__ W2,
                      const float* __restrict__ Wo) {
    int e = (blockIdx.x * 256 + threadIdx.x) * 4;
    const float* src;
    __half* dst;
    int off;
    if (e < 65536)       { src = W1; dst = g_W1; off = e; }
    else if (e < 131072) { src = W2; dst = g_W2; off = e - 65536; }
    else                 { src = Wo; dst = g_Wo; off = e - 131072; }
    float4 v = *(const float4*)(src + off);
    *(uint2*)(dst + off) = make_uint2(packh2(v.x, v.y), packh2(v.z, v.w));
}

// ===========================================================================
// Common tiling constants (R12 config, 4-stage mainloop)
// ===========================================================================
#define LDSB 144                            // pipeline rows: 64 fp16 + pad
#define G_A_PART (128 * LDSB)               // 18432
#define G_B_PART (256 * LDSB)               // 36864
#define G_STAGE (G_A_PART + G_B_PART)       // 55296
#define G_NSTAGE 4
#define G_SMEM (G_NSTAGE * G_STAGE)         // 221184
// FC-phase smem (reuses pipeline region):
#define CLD 528                             // C/h rows: 256 fp16 + 16B pad
#define WB0_OFF 67584                       // 128*528
#define WB1_OFF 104448                      // +256*144
#define NB0_OFF 141312                      // +256*144
#define NB1_OFF 159744                      // +128*144
#define HT_LD 272                           // transposed h rows: 128 fp16 + pad

// Batched-fragment MMA step: issue ALL 6 LDSM first, then 16 MMAs.
#define MMA_STEP(a_base, a_ld, koff, wb, kb)                                   \
    do {                                                                       \
        uint32_t Af[2][4], Bf[4][4];                                           \
        _Pragma("unroll")                                                      \
        for (int mi = 0; mi < 2; mi++)                                         \
            ldsm4(Af[mi], (a_base) + (warp_m + mi * 16 + a_row) * (a_ld) +     \
                           (koff) + (kb) + a_cb);                              \
        _Pragma("unroll")                                                      \
        for (int g = 0; g < 4; g++)                                            \
            ldsm4(Bf[g], (wb) + (warp_n + g * 16 + b_row) * LDSB + (kb) + b_cb); \
        _Pragma("unroll")                                                      \
        for (int g = 0; g < 4; g++)                                            \
            _Pragma("unroll")                                                  \
            for (int mi = 0; mi < 2; mi++) {                                   \
                mma_f16(acc[mi][2 * g],     Af[mi], Bf[g]);                    \
                mma_f16(acc[mi][2 * g + 1], Af[mi], Bf[g] + 2);                \
            }                                                                  \
    } while (0)

// ===========================================================================
// Layer 1 fused: C = dinv*(G@Xt^T); h = relu(C@W1^T+b1);
// out Xt2[b][h][tok] = h^T * dinv.
// ===========================================================================
__global__ void __launch_bounds__(512, 1) aggfc1(
    const __half* __restrict__ G, const __half* __restrict__ Xin,
    const __half* __restrict__ W, const float* __restrict__ bias,
    __half* __restrict__ out)
{
    extern __shared__ char smem[];
    const uint32_t sb = s2u(smem);
    constexpr int NC = N_ / 64;  // 32

    const int tid = threadIdx.x, wid = tid >> 5, lane = tid & 31;
    const int b = blockIdx.z;
    const int m0 = blockIdx.y * 128;
    const int warp_m = (wid & 3) * 32;
    const int warp_n = (wid >> 2) * 64;

    const __half* pA = G + (size_t)b * N_ * N_ + (size_t)m0 * N_;
    const __half* pB = Xin + (size_t)b * H_ * N_;

    float acc[2][8][4];
#pragma unroll
    for (int i = 0; i < 2; i++)
#pragma unroll
        for (int j = 0; j < 8; j++)
#pragma unroll
            for (int q = 0; q < 4; q++) acc[i][j][q] = 0.f;

    auto load_stage = [&](int s, int kc) {
        const int k0 = kc * 64;
        const uint32_t base = sb + s * G_STAGE;
#pragma unroll
        for (int it = 0; it < 6; it++) {
            int c = it * 512 + tid;
            if (c < 1024) {
                int row = c >> 3, seg = c & 7;
                cp16(base + row * LDSB + seg * 16,
                     pA + (size_t)row * N_ + k0 + seg * 8);
            } else {
                int cb = c - 1024;
                int row = cb >> 3, seg = cb & 7;
                cp16(base + G_A_PART + row * LDSB + seg * 16,
                     pB + (size_t)row * N_ + k0 + seg * 8);
            }
        }
    };

    const uint32_t a_row = (uint32_t)(lane & 15);
    const uint32_t a_cb  = (uint32_t)((lane >> 4) * 16);
    const uint32_t b_row = (uint32_t)((lane & 7) + ((lane & 16) ? 8 : 0));
    const uint32_t b_cb  = (uint32_t)((lane & 8) << 1);

    load_stage(0, 0); CP_COMMIT();
    load_stage(1, 1); CP_COMMIT();
    load_stage(2, 2); CP_COMMIT();

    for (int k = 0; k < NC; k++) {
        CP_WAITG2();
        __syncthreads();
        if (k + 3 < NC) load_stage((k + 3) % G_NSTAGE, k + 3);
        CP_COMMIT();

        const uint32_t sA = sb + (k % G_NSTAGE) * G_STAGE;
        const uint32_t sB = sA + G_A_PART;
#pragma unroll
        for (int ks = 0; ks < 4; ks++)
            MMA_STEP(sA, LDSB, 0u, sB, (uint32_t)(ks * 32));
    }

    // ---------------- FC1 phase ----------------
    __syncthreads();
    CP_WAITG0();

    auto load_w = [&](uint32_t buf, int kc) {
        const int k0 = kc * 64;
#pragma unroll
        for (int it = 0; it < 4; it++) {
            int c = it * 512 + tid;
            int row = c >> 3, seg = c & 7;
            cp16(buf + row * LDSB + seg * 16,
                 W + (size_t)row * H_ + k0 + seg * 8);
        }
    };
    load_w(sb + WB0_OFF, 0); CP_COMMIT();
    load_w(sb + WB1_OFF, 1); CP_COMMIT();

    const int colb = warp_n + (lane & 3) * 2;
#pragma unroll
    for (int mi = 0; mi < 2; mi++) {
#pragma unroll
        for (int p = 0; p < 2; p++) {
            const int ml = warp_m + mi * 16 + (lane >> 2) + p * 8;
            const float dv = g_dinv[b * N_ + m0 + ml];
#pragma unroll
            for (int ni = 0; ni < 8; ni++) {
                *(uint32_t*)(smem + ml * CLD + (colb + ni * 8) * 2) =
                    packh2(acc[mi][ni][2 * p] * dv, acc[mi][ni][2 * p + 1] * dv);
            }
        }
    }
#pragma unroll
    for (int i = 0; i < 2; i++)
#pragma unroll
        for (int j = 0; j < 8; j++)
#pragma unroll
            for (int q = 0; q < 4; q++) acc[i][j][q] = 0.f;

    CP_WAITG1();
    __syncthreads();

    auto fc_chunk = [&](int kc, uint32_t wb) {
#pragma unroll
        for (int ks = 0; ks < 4; ks++)
            MMA_STEP(sb, CLD, (uint32_t)(kc * 128), wb, (uint32_t)(ks * 32));
    };

    fc_chunk(0, sb + WB0_OFF);
    __syncthreads();
    load_w(sb + WB0_OFF, 2); CP_COMMIT();
    CP_WAITG1(); __syncthreads();
    fc_chunk(1, sb + WB1_OFF);
    __syncthreads();
    load_w(sb + WB1_OFF, 3); CP_COMMIT();
    CP_WAITG1(); __syncthreads();
    fc_chunk(2, sb + WB0_OFF);
    CP_WAITG0(); __syncthreads();
    fc_chunk(3, sb + WB1_OFF);

    // ---------------- transpose-out ----------------
    __syncthreads();
#pragma unroll
    for (int mi = 0; mi < 2; mi++) {
#pragma unroll
        for (int p = 0; p < 2; p++) {
            const int ml = warp_m + mi * 16 + (lane >> 2) + p * 8;
            const float dv = g_dinv[b * N_ + m0 + ml];
#pragma unroll
            for (int ni = 0; ni < 8; ni++) {
                int c = colb + ni * 8;
                float v0 = fmaxf(acc[mi][ni][2 * p]     + bias[c],     0.f) * dv;
                float v1 = fmaxf(acc[mi][ni][2 * p + 1] + bias[c + 1], 0.f) * dv;
                *(__half*)(smem + c * HT_LD + ml * 2)       = __float2half_rn(v0);
                *(__half*)(smem + (c + 1) * HT_LD + ml * 2) = __float2half_rn(v1);
            }
        }
    }
    __syncthreads();
    const int h = tid >> 1, seg = tid & 1;
    const char* srow = smem + h * HT_LD + seg * 128;
    __half* drow = out + (size_t)(b * H_ + h) * N_ + m0 + seg * 64;
#pragma unroll
    for (int q = 0; q < 8; q++)
        *(uint4*)(drow + q * 8) = *(const uint4*)(srow + q * 16);
}

// ===========================================================================
// Layer 2 fused + output FC:
//   C = dinv*(G@Xt2^T); h = relu(C@W2^T+b2);
//   out = relu([Nf | h] @ Wo^T + bout)  (f32, final)
// ===========================================================================
__global__ void __launch_bounds__(512, 1) aggfc2(
    const __half* __restrict__ G, const __half* __restrict__ Xin,
    const __half* __restrict__ W2h, const float* __restrict__ b2,
    const __half* __restrict__ Nf, const __half* __restrict__ Wo,
    const float* __restrict__ bout, float* __restrict__ out)
{
    extern __shared__ char smem[];
    const uint32_t sb = s2u(smem);
    constexpr int NC = N_ / 64;  // 32

    const int tid = threadIdx.x, wid = tid >> 5, lane = tid & 31;
    const int b = blockIdx.z;
    const int m0 = blockIdx.y * 128;
    const int warp_m = (wid & 3) * 32;
    const int warp_n = (wid >> 2) * 64;

    const __half* pA = G + (size_t)b * N_ * N_ + (size_t)m0 * N_;
    const __half* pB = Xin + (size_t)b * H_ * N_;

    float acc[2][8][4];
#pragma unroll
    for (int i = 0; i < 2; i++)
#pragma unroll
        for (int j = 0; j < 8; j++)
#pragma unroll
            for (int q = 0; q < 4; q++) acc[i][j][q] = 0.f;

    auto load_stage = [&](int s, int kc) {
        const int k0 = kc * 64;
        const uint32_t base = sb + s * G_STAGE;
#pragma unroll
        for (int it = 0; it < 6; it++) {
            int c = it * 512 + tid;
            if (c < 1024) {
                int row = c >> 3, seg = c & 7;
                cp16(base + row * LDSB + seg * 16,
                     pA + (size_t)row * N_ + k0 + seg * 8);
            } else {
                int cb = c - 1024;
                int row = cb >> 3, seg = cb & 7;
                cp16(base + G_A_PART + row * LDSB + seg * 16,
                     pB + (size_t)row * N_ + k0 + seg * 8);
            }
        }
    };

    const uint32_t a_row = (uint32_t)(lane & 15);
    const uint32_t a_cb  = (uint32_t)((lane >> 4) * 16);
    const uint32_t b_row = (uint32_t)((lane & 7) + ((lane & 16) ? 8 : 0));
    const uint32_t b_cb  = (uint32_t)((lane & 8) << 1);

    load_stage(0, 0); CP_COMMIT();
    load_stage(1, 1); CP_COMMIT();
    load_stage(2, 2); CP_COMMIT();

    for (int k = 0; k < NC; k++) {
        CP_WAITG2();
        __syncthreads();
        if (k + 3 < NC) load_stage((k + 3) % G_NSTAGE, k + 3);
        CP_COMMIT();

        const uint32_t sA = sb + (k % G_NSTAGE) * G_STAGE;
        const uint32_t sB = sA + G_A_PART;
#pragma unroll
        for (int ks = 0; ks < 4; ks++)
            MMA_STEP(sA, LDSB, 0u, sB, (uint32_t)(ks * 32));
    }

    // ---------------- FC2 phase ----------------
    __syncthreads();
    CP_WAITG0();

    auto load_w2 = [&](uint32_t buf, int kc) {
        const int k0 = kc * 64;
#pragma unroll
        for (int it = 0; it < 4; it++) {
            int c = it * 512 + tid;
            int row = c >> 3, seg = c & 7;
            cp16(buf + row * LDSB + seg * 16,
                 W2h + (size_t)row * H_ + k0 + seg * 8);
        }
    };
    load_w2(sb + WB0_OFF, 0); CP_COMMIT();
    load_w2(sb + WB1_OFF, 1); CP_COMMIT();

    const int colb = warp_n + (lane & 3) * 2;
#pragma unroll
    for (int mi = 0; mi < 2; mi++) {
#pragma unroll
        for (int p = 0; p < 2; p++) {
            const int ml = warp_m + mi * 16 + (lane >> 2) + p * 8;
            const float dv = g_dinv[b * N_ + m0 + ml];
#pragma unroll
            for (int ni = 0; ni < 8; ni++) {
                *(uint32_t*)(smem + ml * CLD + (colb + ni * 8) * 2) =
                    packh2(acc[mi][ni][2 * p] * dv, acc[mi][ni][2 * p + 1] * dv);
            }
        }
    }
#pragma unroll
    for (int i = 0; i < 2; i++)
#pragma unroll
        for (int j = 0; j < 8; j++)
#pragma unroll
            for (int q = 0; q < 4; q++) acc[i][j][q] = 0.f;

    CP_WAITG1();
    __syncthreads();

    auto gen_chunk = [&](uint32_t a_base, uint32_t a_ld, uint32_t koff, uint32_t wb) {
#pragma unroll
        for (int ks = 0; ks < 4; ks++)
            MMA_STEP(a_base, a_ld, koff, wb, (uint32_t)(ks * 32));
    };

    gen_chunk(sb, CLD, 0,   sb + WB0_OFF);
    __syncthreads();
    load_w2(sb + WB0_OFF, 2); CP_COMMIT();
    CP_WAITG1(); __syncthreads();
    gen_chunk(sb, CLD, 128, sb + WB1_OFF);
    __syncthreads();
    load_w2(sb + WB1_OFF, 3); CP_COMMIT();
    CP_WAITG1(); __syncthreads();
    gen_chunk(sb, CLD, 256, sb + WB0_OFF);
    CP_WAITG0(); __syncthreads();
    gen_chunk(sb, CLD, 384, sb + WB1_OFF);

    // ---------------- fcout phase: out = relu([Nf|h] @ Wo^T + bout) --------
    __syncthreads();   // all warps done with CLD (C) and W buffers

    auto load_wo = [&](uint32_t buf, int kc) {
        const int k0 = kc * 64;
#pragma unroll
        for (int it = 0; it < 4; it++) {
            int c = it * 512 + tid;
            int row = c >> 3, seg = c & 7;
            cp16(buf + row * LDSB + seg * 16,
                 Wo + (size_t)row * (2 * H_) + k0 + seg * 8);
        }
    };
    auto load_n = [&](uint32_t buf, int kc) {
        const int k0 = kc * 64;
#pragma unroll
        for (int it = 0; it < 2; it++) {
            int c = it * 512 + tid;
            int row = c >> 3, seg = c & 7;
            cp16(buf + row * LDSB + seg * 16,
                 Nf + (size_t)(b * N_ + m0 + row) * H_ + k0 + seg * 8);
        }
    };
    load_wo(sb + WB0_OFF, 0); load_n(sb + NB0_OFF, 0); CP_COMMIT();
    load_wo(sb + WB1_OFF, 1); load_n(sb + NB1_OFF, 1); CP_COMMIT();

    // h = relu(acc + b2) -> CLD region; re-zero acc
#pragma unroll
    for (int mi = 0; mi < 2; mi++) {
#pragma unroll
        for (int p = 0; p < 2; p++) {
            const int ml = warp_m + mi * 16 + (lane >> 2) + p * 8;
#pragma unroll
            for (int ni = 0; ni < 8; ni++) {
                int c = colb + ni * 8;
                *(uint32_t*)(smem + ml * CLD + c * 2) =
                    packh2(fmaxf(acc[mi][ni][2 * p]     + b2[c],     0.f),
                           fmaxf(acc[mi][ni][2 * p + 1] + b2[c + 1], 0.f));
            }
        }
    }
#pragma unroll
    for (int i = 0; i < 2; i++)
#pragma unroll
        for (int j = 0; j < 8; j++)
#pragma unroll
            for (int q = 0; q < 4; q++) acc[i][j][q] = 0.f;

    CP_WAITG1();
    __syncthreads();   // chunk0 (Wo+N) arrived, h visible

    for (int kc = 0; kc < 8; kc++) {
        const uint32_t wb = sb + ((kc & 1) ? WB1_OFF : WB0_OFF);
        if (kc < 4) {
            const uint32_t nb = sb + ((kc & 1) ? NB1_OFF : NB0_OFF);
            gen_chunk(nb, LDSB, 0, wb);
        } else {
            gen_chunk(sb, CLD, (uint32_t)(kc - 4) * 128, wb);
        }
        if (kc + 2 < 8) {
            __syncthreads();               // buffer (kc&1) free to overwrite
            load_wo(sb + ((kc & 1) ? WB1_OFF : WB0_OFF), kc + 2);
            if (kc + 2 < 4) load_n(sb + ((kc & 1) ? NB1_OFF : NB0_OFF), kc + 2);
            CP_COMMIT();
            CP_WAITG1(); __syncthreads();  // chunk kc+1 ready
        } else if (kc + 1 < 8) {
            CP_WAITG0(); __syncthreads();  // final chunk ready
        }
    }

    // ---------------- final epilogue: f32 out ----------------
#pragma unroll
    for (int mi = 0; mi < 2; mi++) {
#pragma unroll
        for (int p = 0; p < 2; p++) {
            const int ml = warp_m + mi * 16 + (lane >> 2) + p * 8;
            const size_t orow = (size_t)(b * N_ + m0 + ml) * H_;
#pragma unroll
            for (int ni = 0; ni < 8; ni++) {
                int c = colb + ni * 8;
                float2 o;
                o.x = fmaxf(acc[mi][ni][2 * p]     + bout[c],     0.f);
                o.y = fmaxf(acc[mi][ni][2 * p + 1] + bout[c + 1], 0.f);
                *(float2*)(out + orow + c) = o;
            }
        }
    }
}

// ---------------------------------------------------------------------------
// Launch — 5 kernels total
// ---------------------------------------------------------------------------
extern "C" void kernel_launch(void* const* d_in, const int* in_sizes, int n_in,
                              void* d_out, int out_size) {
    const float* node  = (const float*)d_in[0];
    const float* graph = (const float*)d_in[1];
    const float* W1    = (const float*)d_in[2];
    const float* b1    = (const float*)d_in[3];
    const float* W2    = (const float*)d_in[4];
    const float* b2    = (const float*)d_in[5];
    const float* Wout  = (const float*)d_in[6];
    const float* bout  = (const float*)d_in[7];
    float* out = (float*)d_out;

    __half *Gf16, *Xt, *Xt2, *Nf, *W1h, *W2h, *Woh;
    cudaGetSymbolAddress((void**)&Gf16, g_Gf16);
    cudaGetSymbolAddress((void**)&Xt, g_Xt);
    cudaGetSymbolAddress((void**)&Xt2, g_Xt2);
    cudaGetSymbolAddress((void**)&Nf, g_Nf);
    cudaGetSymbolAddress((void**)&W1h, g_W1);
    cudaGetSymbolAddress((void**)&W2h, g_W2);
    cudaGetSymbolAddress((void**)&Woh, g_Wo);

    cudaFuncSetAttribute(aggfc1, cudaFuncAttributeMaxDynamicSharedMemorySize, G_SMEM);
    cudaFuncSetAttribute(aggfc2, cudaFuncAttributeMaxDynamicSharedMemorySize, G_SMEM);

    dim3 gAgg(1, N_ / 128, B_);       // 128 CTAs
    dim3 gXt(64, 8, 8), bXt(32, 8);

    graph_conv<<<B_ * N_, 256>>>(graph);                               // 0
    prep_node<<<gXt, bXt>>>(node);                                     // 1
    wconv<<<256, 256>>>(W1, W2, Wout);                                 // 2
    aggfc1<<<gAgg, 512, G_SMEM>>>(Gf16, Xt, W1h, b1, Xt2);             // 3
    aggfc2<<<gAgg, 512, G_SMEM>>>(Gf16, Xt2, W2h, b2,
                                  Nf, Woh, bout, out);                 // 4
}